// round 1
// baseline (speedup 1.0000x reference)
#include <cuda_runtime.h>
#include <cuda_bf16.h>
#include <cstdint>

// Problem constants (fixed by the dataset)
#define ND 50000
#define NG 100000
#define NE 600000
#define DIN 128
#define HID 64

// ---------------- static scratch (no runtime allocation allowed) ----------------
__device__ __align__(16) float g_td[(size_t)ND * 128];   // disease transform: [a | r]
__device__ __align__(16) float g_tg[(size_t)NG * 128];   // gene transform:    [a | r]
__device__ __align__(16) float g_d1[(size_t)ND * 64];
__device__ __align__(16) float g_g1[(size_t)NG * 64];

__device__ int g_rp_g[NG + 1];
__device__ int g_rp_d[ND + 1];
__device__ int g_cur_g[NG];      // doubles as counts, then cursors
__device__ int g_cur_d[ND];
__device__ int g_col_dg[NE];
__device__ int g_col_gd[NE];
__device__ int g_bs_g[64];
__device__ int g_bs_d[64];

// ---------------- f32x2 helpers ----------------
__device__ __forceinline__ unsigned long long pack2(float lo, float hi) {
    unsigned long long r;
    asm("mov.b64 %0, {%1, %2};" : "=l"(r) : "f"(lo), "f"(hi));
    return r;
}
__device__ __forceinline__ unsigned long long ffma2(unsigned long long a,
                                                    unsigned long long b,
                                                    unsigned long long c) {
    unsigned long long d;
    asm("fma.rn.f32x2 %0, %1, %2, %3;" : "=l"(d) : "l"(a), "l"(b), "l"(c));
    return d;
}

// ---------------- CSR build ----------------
__global__ void zero_counts_kernel() {
    int i = blockIdx.x * blockDim.x + threadIdx.x;
    if (i < NG) g_cur_g[i] = 0;
    if (i < ND) g_cur_d[i] = 0;
}

__global__ void hist_kernel(const int* __restrict__ dst, int e, int* __restrict__ cnt) {
    int i = blockIdx.x * blockDim.x + threadIdx.x;
    if (i < e) atomicAdd(&cnt[dst[i]], 1);
}

// block partial sums over chunks of 2048
__global__ void scan_block_sums(const int* __restrict__ cnt, int n, int* __restrict__ bsums) {
    __shared__ int sdata[256];
    int tid = threadIdx.x;
    int base = blockIdx.x * 2048;
    int s = 0;
    for (int i = tid; i < 2048; i += 256) {
        int idx = base + i;
        if (idx < n) s += cnt[idx];
    }
    sdata[tid] = s;
    __syncthreads();
    for (int o = 128; o > 0; o >>= 1) {
        if (tid < o) sdata[tid] += sdata[tid + o];
        __syncthreads();
    }
    if (tid == 0) bsums[blockIdx.x] = sdata[0];
}

// exclusive scan of <=64 block sums
__global__ void scan_small(int* __restrict__ bs, int nb) {
    __shared__ int s[64];
    int tid = threadIdx.x;
    int orig = (tid < nb) ? bs[tid] : 0;
    s[tid] = orig;
    __syncthreads();
    for (int o = 1; o < 64; o <<= 1) {
        int v = (tid >= o) ? s[tid - o] : 0;
        __syncthreads();
        s[tid] += v;
        __syncthreads();
    }
    if (tid < nb) bs[tid] = s[tid] - orig;  // exclusive
}

// finalize: write row_ptr and cursors (cnt may alias cursor)
__global__ void scan_finalize(const int* __restrict__ cnt, int n,
                              const int* __restrict__ bsums,
                              int* __restrict__ row_ptr, int* __restrict__ cursor) {
    __shared__ int sh[256];
    int tid = threadIdx.x;
    int base = blockIdx.x * 2048 + tid * 8;
    int v[8];
    int tsum = 0;
#pragma unroll
    for (int i = 0; i < 8; i++) {
        int idx = base + i;
        v[i] = (idx < n) ? cnt[idx] : 0;
        tsum += v[i];
    }
    sh[tid] = tsum;
    __syncthreads();
    for (int o = 1; o < 256; o <<= 1) {
        int add = (tid >= o) ? sh[tid - o] : 0;
        __syncthreads();
        sh[tid] += add;
        __syncthreads();
    }
    int run = sh[tid] - tsum + bsums[blockIdx.x];
#pragma unroll
    for (int i = 0; i < 8; i++) {
        int idx = base + i;
        if (idx < n) {
            cursor[idx] = run;
            run += v[i];
            row_ptr[idx + 1] = run;
        }
    }
    if (blockIdx.x == 0 && tid == 0) row_ptr[0] = 0;
}

__global__ void scatter_kernel(const int* __restrict__ src, const int* __restrict__ dst,
                               int e, int* __restrict__ cursor, int* __restrict__ col) {
    int i = blockIdx.x * blockDim.x + threadIdx.x;
    if (i < e) {
        int p = atomicAdd(&cursor[dst[i]], 1);
        col[p] = src[i];
    }
}

// ---------------- fused dual GEMM: out[N,128] = X[N,K] @ [Wa | Wb]  ----------------
// Wa, Wb are [K,64] row-major. Block = 64 rows, 256 threads, FFMA2 inner loop.
template <int K>
__global__ __launch_bounds__(256) void gemm_dual(const float* __restrict__ X,
                                                 const float* __restrict__ Wa,
                                                 const float* __restrict__ Wb,
                                                 float* __restrict__ out, int N) {
    extern __shared__ float sm[];
    float* ws = sm;            // [K][128]
    float* xs = sm + K * 128;  // [64][K]

    int tid = threadIdx.x;
    // load weights: ws[k][c] = c<64 ? Wa[k][c] : Wb[k][c-64]
    for (int i = tid; i < K * 64; i += 256) {
        int k = i / 64, c = i % 64;
        ws[k * 128 + c] = Wa[i];
        ws[k * 128 + 64 + c] = Wb[i];
    }
    int row0 = blockIdx.x * 64;
    const int vecPerRow = K / 4;
    for (int i = tid; i < 64 * vecPerRow; i += 256) {
        int r = i / vecPerRow;
        int k = (i % vecPerRow) * 4;
        int gr = row0 + r;
        float4 v = make_float4(0.f, 0.f, 0.f, 0.f);
        if (gr < N) v = *(const float4*)(X + (size_t)gr * K + k);
        *(float4*)(&xs[r * K + k]) = v;
    }
    __syncthreads();

    const int cx = tid & 31;   // lane: column pair group
    const int ry = tid >> 5;   // warp: row group (8 rows each)

    unsigned long long acc[8][2];
#pragma unroll
    for (int j = 0; j < 8; j++) { acc[j][0] = 0ULL; acc[j][1] = 0ULL; }

#pragma unroll 4
    for (int k = 0; k < K; k++) {
        unsigned long long w0 = *(const unsigned long long*)(ws + k * 128 + 2 * cx);
        unsigned long long w1 = *(const unsigned long long*)(ws + k * 128 + 64 + 2 * cx);
#pragma unroll
        for (int j = 0; j < 8; j++) {
            float xv = xs[(ry * 8 + j) * K + k];
            unsigned long long x2 = pack2(xv, xv);
            acc[j][0] = ffma2(x2, w0, acc[j][0]);
            acc[j][1] = ffma2(x2, w1, acc[j][1]);
        }
    }

#pragma unroll
    for (int j = 0; j < 8; j++) {
        int gr = row0 + ry * 8 + j;
        if (gr < N) {
            *(unsigned long long*)(out + (size_t)gr * 128 + 2 * cx) = acc[j][0];
            *(unsigned long long*)(out + (size_t)gr * 128 + 64 + 2 * cx) = acc[j][1];
        }
    }
}

// ---------------- CSR mean-aggregate + bias + self  ----------------
// out[n][d] = mean_e tsrc[col[e]][d] + bias[d] + tself[n][64+d]
__global__ void aggregate_kernel(const float* __restrict__ tsrc,
                                 const float* __restrict__ tself,
                                 const float* __restrict__ bias,
                                 const int* __restrict__ rp,
                                 const int* __restrict__ col,
                                 float* __restrict__ out, int n_dst) {
    int t = blockIdx.x * blockDim.x + threadIdx.x;
    int n = t >> 6;
    int d = t & 63;
    if (n >= n_dst) return;
    int beg = rp[n], end = rp[n + 1];
    float acc = 0.f;
    for (int e = beg; e < end; e++) {
        acc += __ldg(&tsrc[(size_t)col[e] * 128 + d]);
    }
    float inv = (end > beg) ? 1.f / (float)(end - beg) : 0.f;
    out[(size_t)n * 64 + d] = acc * inv + bias[d] + tself[(size_t)n * 128 + 64 + d];
}

// ---------------- host launcher ----------------
extern "C" void kernel_launch(void* const* d_in, const int* in_sizes, int n_in,
                              void* d_out, int out_size) {
    const float* x_d   = (const float*)d_in[0];
    const float* x_g   = (const float*)d_in[1];
    const int* src_dg  = (const int*)d_in[2];
    const int* dst_dg  = (const int*)d_in[3];
    const int* src_gd  = (const int*)d_in[4];
    const int* dst_gd  = (const int*)d_in[5];
    const float* Wl1_dg = (const float*)d_in[6];
    const float* bl1_dg = (const float*)d_in[7];
    const float* Wr1_dg = (const float*)d_in[8];
    const float* Wl1_gd = (const float*)d_in[9];
    const float* bl1_gd = (const float*)d_in[10];
    const float* Wr1_gd = (const float*)d_in[11];
    const float* Wl2_dg = (const float*)d_in[12];
    const float* bl2_dg = (const float*)d_in[13];
    const float* Wr2_dg = (const float*)d_in[14];
    const float* Wl2_gd = (const float*)d_in[15];
    const float* bl2_gd = (const float*)d_in[16];
    const float* Wr2_gd = (const float*)d_in[17];
    float* out = (float*)d_out;

    int E = in_sizes[2];
    if (E > NE) E = NE;

    float *td, *tg, *d1, *g1;
    int *rpg, *rpd, *curg, *curd, *coldg, *colgd, *bsg, *bsd;
    cudaGetSymbolAddress((void**)&td, g_td);
    cudaGetSymbolAddress((void**)&tg, g_tg);
    cudaGetSymbolAddress((void**)&d1, g_d1);
    cudaGetSymbolAddress((void**)&g1, g_g1);
    cudaGetSymbolAddress((void**)&rpg, g_rp_g);
    cudaGetSymbolAddress((void**)&rpd, g_rp_d);
    cudaGetSymbolAddress((void**)&curg, g_cur_g);
    cudaGetSymbolAddress((void**)&curd, g_cur_d);
    cudaGetSymbolAddress((void**)&coldg, g_col_dg);
    cudaGetSymbolAddress((void**)&colgd, g_col_gd);
    cudaGetSymbolAddress((void**)&bsg, g_bs_g);
    cudaGetSymbolAddress((void**)&bsd, g_bs_d);

    const int smem128 = (128 * 128 + 64 * 128) * sizeof(float);  // 96 KB
    const int smem64  = (64 * 128 + 64 * 64) * sizeof(float);    // 48 KB
    cudaFuncSetAttribute(gemm_dual<128>, cudaFuncAttributeMaxDynamicSharedMemorySize, smem128);
    cudaFuncSetAttribute(gemm_dual<64>, cudaFuncAttributeMaxDynamicSharedMemorySize, smem64);

    const int nb_g = (NG + 2047) / 2048;  // 49
    const int nb_d = (ND + 2047) / 2048;  // 25
    const int eblocks = (E + 255) / 256;

    // ---- CSR build (both directions) ----
    zero_counts_kernel<<<(NG + 255) / 256, 256>>>();
    hist_kernel<<<eblocks, 256>>>(dst_dg, E, curg);
    hist_kernel<<<eblocks, 256>>>(dst_gd, E, curd);
    scan_block_sums<<<nb_g, 256>>>(curg, NG, bsg);
    scan_small<<<1, 64>>>(bsg, nb_g);
    scan_finalize<<<nb_g, 256>>>(curg, NG, bsg, rpg, curg);
    scan_block_sums<<<nb_d, 256>>>(curd, ND, bsd);
    scan_small<<<1, 64>>>(bsd, nb_d);
    scan_finalize<<<nb_d, 256>>>(curd, ND, bsd, rpd, curd);
    scatter_kernel<<<eblocks, 256>>>(src_dg, dst_dg, E, curg, coldg);
    scatter_kernel<<<eblocks, 256>>>(src_gd, dst_gd, E, curd, colgd);

    // ---- layer 1: transform-first (a = lin_l input, r = lin_r self part) ----
    // t_d = x_d @ [Wl1_dg | Wr1_gd];  t_g = x_g @ [Wl1_gd | Wr1_dg]
    gemm_dual<128><<<(ND + 63) / 64, 256, smem128>>>(x_d, Wl1_dg, Wr1_gd, td, ND);
    gemm_dual<128><<<(NG + 63) / 64, 256, smem128>>>(x_g, Wl1_gd, Wr1_dg, tg, NG);

    // g1 = mean_{dg}(a_d) + bl1_dg + r_g ;  d1 = mean_{gd}(a_g) + bl1_gd + r_d
    aggregate_kernel<<<(NG * 64 + 255) / 256, 256>>>(td, tg, bl1_dg, rpg, coldg, g1, NG);
    aggregate_kernel<<<(ND * 64 + 255) / 256, 256>>>(tg, td, bl1_gd, rpd, colgd, d1, ND);

    // ---- layer 2 ----
    // t2_d = d1 @ [Wl2_dg | Wr2_gd];  t2_g = g1 @ [Wl2_gd | Wr2_dg]
    gemm_dual<64><<<(ND + 63) / 64, 256, smem64>>>(d1, Wl2_dg, Wr2_gd, td, ND);
    gemm_dual<64><<<(NG + 63) / 64, 256, smem64>>>(g1, Wl2_gd, Wr2_dg, tg, NG);

    // g2 -> out[ND*64 ..], d2 -> out[0 ..]
    aggregate_kernel<<<(NG * 64 + 255) / 256, 256>>>(td, tg, bl2_dg, rpg, coldg,
                                                     out + (size_t)ND * 64, NG);
    aggregate_kernel<<<(ND * 64 + 255) / 256, 256>>>(tg, td, bl2_gd, rpd, colgd,
                                                     out, ND);
}